// round 1
// baseline (speedup 1.0000x reference)
#include <cuda_runtime.h>
#include <math.h>

#define Nn 50000
#define Ee 800000
#define Hh 128
#define Gg 512
#define NG 50
#define NI 6
#define TT 8192

#define TAB_DMAX 8.6605f
#define DTf      (TAB_DMAX / 8191.0f)
#define INV_DT   (8191.0f / TAB_DMAX)
#define GDELTA   (10.0f / 49.0f)
#define PI_OC    0.3141592653589793f

// ---------------- scratch (static device globals; no allocs allowed) -------
__device__ __align__(16) float g_h  [Nn * Hh];
__device__ __align__(16) float g_x  [Nn * Hh];
__device__ __align__(16) float g_x2 [Nn * Hh];
__device__ __align__(16) float g_agg[Nn * Hh];
__device__ __align__(16) float g_h2 [Nn * 64];
__device__ __align__(16) float g_tab[(size_t)NI * TT * Hh];   // 25.2 MB
__device__ int   g_eidx [Ee];
__device__ float g_efrac[Ee];

__device__ __forceinline__ float sspf(float v) {
    float sp = (v > 15.0f) ? v : log1pf(expf(v));
    return sp - 0.6931471805599453f;
}

// ---------------- h = emb[z] ------------------------------------------------
__global__ void k_embed(const float* __restrict__ emb, const int* __restrict__ z) {
    int i = blockIdx.x * blockDim.x + threadIdx.x;
    if (i >= Nn * 32) return;
    int n = i >> 5, c = i & 31;
    ((float4*)g_h)[i] = ((const float4*)emb)[(size_t)z[n] * 32 + c];
}

// ---------------- per-edge distance -> table index + frac -------------------
__global__ void k_geom(const float* __restrict__ pos,
                       const int* __restrict__ row, const int* __restrict__ col) {
    int e = blockIdx.x * blockDim.x + threadIdx.x;
    if (e >= Ee) return;
    int r = row[e], c = col[e];
    float dx = pos[3 * r + 0] - pos[3 * c + 0];
    float dy = pos[3 * r + 1] - pos[3 * c + 1];
    float dz = pos[3 * r + 2] - pos[3 * c + 2];
    float d = sqrtf(fmaf(dx, dx, fmaf(dy, dy, fmaf(dz, dz, 1e-12f))));
    float tp = d * INV_DT;
    int i0 = (int)tp;
    if (i0 > TT - 2) i0 = TT - 2;
    g_eidx[e]  = i0;
    g_efrac[e] = tp - (float)i0;
}

// ---------------- build filter tables: tab[i][t][:] = filter_i(d_t) ---------
// block = 128 threads (4 warps); each warp processes 8 table rows per pass,
// lane owns 4 features. Weights staged in smem.
__global__ void k_table(const float* __restrict__ w1, const float* __restrict__ b1,
                        const float* __restrict__ w2, const float* __restrict__ b2) {
    extern __shared__ float sm[];
    float* w1s = sm;                    // NG*128
    float* w2s = w1s + NG * 128;        // 128*128
    float* b1s = w2s + 128 * 128;       // 128
    float* b2s = b1s + 128;             // 128
    float* ts  = b2s + 128;             // 4*8*128
    float* rs  = ts + 4 * 8 * 128;      // 4*8*NG

    int it = blockIdx.y;
    const float* W1 = w1 + (size_t)it * NG * 128;
    const float* W2 = w2 + (size_t)it * 128 * 128;
    for (int j = threadIdx.x; j < NG * 128; j += blockDim.x) w1s[j] = W1[j];
    for (int j = threadIdx.x; j < 128 * 128; j += blockDim.x) w2s[j] = W2[j];
    if (threadIdx.x < 128) {
        b1s[threadIdx.x] = b1[it * 128 + threadIdx.x];
        b2s[threadIdx.x] = b2[it * 128 + threadIdx.x];
    }
    __syncthreads();

    int warp = threadIdx.x >> 5, lane = threadIdx.x & 31;
    float* tw = ts + warp * 8 * 128;
    float* rw = rs + warp * 8 * NG;
    const float GCO = -0.5f / (GDELTA * GDELTA);

    for (int base = (blockIdx.x * 4 + warp) * 8; base < TT; base += gridDim.x * 32) {
        // stage rbf rows for this warp's 8 table points
        for (int j = lane; j < 8 * NG; j += 32) {
            int e = j / NG, k = j - e * NG;
            float d = (float)(base + e) * DTf;
            float u = d - (float)k * GDELTA;
            rw[j] = expf(GCO * u * u);
        }
        __syncwarp();

        float4 acc[8];
        float4 bb = *(const float4*)&b1s[4 * lane];
        #pragma unroll
        for (int e = 0; e < 8; e++) acc[e] = bb;
        for (int k = 0; k < NG; k++) {
            float4 w = *(const float4*)&w1s[k * 128 + 4 * lane];
            #pragma unroll
            for (int e = 0; e < 8; e++) {
                float r = rw[e * NG + k];
                acc[e].x = fmaf(r, w.x, acc[e].x);
                acc[e].y = fmaf(r, w.y, acc[e].y);
                acc[e].z = fmaf(r, w.z, acc[e].z);
                acc[e].w = fmaf(r, w.w, acc[e].w);
            }
        }
        #pragma unroll
        for (int e = 0; e < 8; e++) {
            float4 v;
            v.x = sspf(acc[e].x); v.y = sspf(acc[e].y);
            v.z = sspf(acc[e].z); v.w = sspf(acc[e].w);
            *(float4*)&tw[e * 128 + 4 * lane] = v;
        }
        __syncwarp();

        float4 bb2 = *(const float4*)&b2s[4 * lane];
        #pragma unroll
        for (int e = 0; e < 8; e++) acc[e] = bb2;
        for (int k = 0; k < 128; k++) {
            float4 w = *(const float4*)&w2s[k * 128 + 4 * lane];
            #pragma unroll
            for (int e = 0; e < 8; e++) {
                float t = tw[e * 128 + k];
                acc[e].x = fmaf(t, w.x, acc[e].x);
                acc[e].y = fmaf(t, w.y, acc[e].y);
                acc[e].z = fmaf(t, w.z, acc[e].z);
                acc[e].w = fmaf(t, w.w, acc[e].w);
            }
        }
        #pragma unroll
        for (int e = 0; e < 8; e++) {
            float d = (float)(base + e) * DTf;
            float Cc = 0.5f * (cosf(d * PI_OC) + 1.0f);
            float4 v = acc[e];
            v.x *= Cc; v.y *= Cc; v.z *= Cc; v.w *= Cc;
            *(float4*)&g_tab[((size_t)it * TT + (base + e)) * 128 + 4 * lane] = v;
        }
        __syncwarp();
    }
}

// ---------------- generic node GEMM: out = op(in[M,128] @ W[128,NOUT] + b) --
// 256 threads, 64-row tile, register tile TM x 4, weights + A tile in smem.
template<int NOUT, bool BIAS, bool ACT, bool RES>
__global__ void k_ngemm(const float* __restrict__ in, const float* __restrict__ W,
                        const float* __restrict__ bias, float* __restrict__ out, int M) {
    constexpr int CG = NOUT / 4;
    constexpr int RG = 256 / CG;
    constexpr int TM = 64 / RG;
    extern __shared__ float sm[];
    float* Ws = sm;                 // 128*NOUT
    float* Bs = Ws + 128 * NOUT;    // NOUT
    float* As = Bs + NOUT;          // 64*128

    for (int j = threadIdx.x; j < (128 * NOUT) / 4; j += 256)
        ((float4*)Ws)[j] = ((const float4*)W)[j];
    if (BIAS) {
        for (int j = threadIdx.x; j < NOUT; j += 256) Bs[j] = bias[j];
    }
    int colg = threadIdx.x % CG;
    int rowg = threadIdx.x / CG;

    for (int mBase = blockIdx.x * 64; mBase < M; mBase += gridDim.x * 64) {
        __syncthreads();
        for (int j = threadIdx.x; j < 2048; j += 256) {
            int r = j >> 5;
            int gr = mBase + r;
            ((float4*)As)[j] = (gr < M) ? ((const float4*)in)[(size_t)gr * 32 + (j & 31)]
                                        : make_float4(0.f, 0.f, 0.f, 0.f);
        }
        __syncthreads();

        float4 acc[TM];
        #pragma unroll
        for (int r = 0; r < TM; r++) acc[r] = make_float4(0.f, 0.f, 0.f, 0.f);
        #pragma unroll 4
        for (int k = 0; k < 128; k++) {
            float4 w = *(const float4*)&Ws[k * NOUT + 4 * colg];
            #pragma unroll
            for (int r = 0; r < TM; r++) {
                float a = As[(rowg * TM + r) * 128 + k];
                acc[r].x = fmaf(a, w.x, acc[r].x);
                acc[r].y = fmaf(a, w.y, acc[r].y);
                acc[r].z = fmaf(a, w.z, acc[r].z);
                acc[r].w = fmaf(a, w.w, acc[r].w);
            }
        }
        #pragma unroll
        for (int r = 0; r < TM; r++) {
            int gr = mBase + rowg * TM + r;
            if (gr < M) {
                float4 v = acc[r];
                if (BIAS) {
                    v.x += Bs[4 * colg + 0]; v.y += Bs[4 * colg + 1];
                    v.z += Bs[4 * colg + 2]; v.w += Bs[4 * colg + 3];
                }
                if (ACT) { v.x = sspf(v.x); v.y = sspf(v.y); v.z = sspf(v.z); v.w = sspf(v.w); }
                float4* dst = (float4*)(out + (size_t)gr * NOUT + 4 * colg);
                if (RES) { float4 o = *dst; v.x += o.x; v.y += o.y; v.z += o.z; v.w += o.w; }
                *dst = v;
            }
        }
    }
}

// ---------------- edge message: agg[row] += x[col] * lerp(tab, d) -----------
// one warp per edge, lane owns 4 features (float4 path)
__global__ void k_edge(int it, const int* __restrict__ row, const int* __restrict__ col) {
    const float* tab = g_tab + (size_t)it * TT * Hh;
    int lane = threadIdx.x & 31;
    int gw = (blockIdx.x * blockDim.x + threadIdx.x) >> 5;
    int nw = (gridDim.x * blockDim.x) >> 5;
    for (int e = gw; e < Ee; e += nw) {
        int   i0 = g_eidx[e];
        float fr = g_efrac[e];
        int cs = col[e];
        int rt = row[e];
        float4 a  = ((const float4*)(tab + (size_t)i0 * Hh))[lane];
        float4 b  = ((const float4*)(tab + (size_t)(i0 + 1) * Hh))[lane];
        float4 x4 = ((const float4*)(g_x + (size_t)cs * Hh))[lane];
        float4 m;
        m.x = x4.x * fmaf(fr, b.x - a.x, a.x);
        m.y = x4.y * fmaf(fr, b.y - a.y, a.y);
        m.z = x4.z * fmaf(fr, b.z - a.z, a.z);
        m.w = x4.w * fmaf(fr, b.w - a.w, a.w);
        float* dst = g_agg + (size_t)rt * Hh + 4 * lane;
        atomicAdd(dst + 0, m.x);
        atomicAdd(dst + 1, m.y);
        atomicAdd(dst + 2, m.z);
        atomicAdd(dst + 3, m.w);
    }
}

// ---------------- readout: energy[batch[n]] += h2[n] . ow2 + ob2 ------------
__global__ void k_energy(const float* __restrict__ ow2, const float* __restrict__ ob2,
                         const int* __restrict__ batch, float* __restrict__ out) {
    int idx = blockIdx.x * blockDim.x + threadIdx.x;
    int n = idx >> 5;
    if (n >= Nn) return;
    int lane = idx & 31;
    float2 hv = ((const float2*)(g_h2 + (size_t)n * 64))[lane];
    float2 wv = ((const float2*)ow2)[lane];
    float s = hv.x * wv.x + hv.y * wv.y;
    #pragma unroll
    for (int o = 16; o; o >>= 1) s += __shfl_down_sync(0xffffffffu, s, o);
    if (lane == 0) atomicAdd(&out[batch[n]], s + ob2[0]);
}

// ---------------------------------------------------------------------------
extern "C" void kernel_launch(void* const* d_in, const int* in_sizes, int n_in,
                              void* d_out, int out_size) {
    const float* pos   = (const float*)d_in[0];
    const float* emb   = (const float*)d_in[1];
    const float* w1    = (const float*)d_in[2];
    const float* b1    = (const float*)d_in[3];
    const float* w2    = (const float*)d_in[4];
    const float* b2    = (const float*)d_in[5];
    const float* lin1w = (const float*)d_in[6];
    const float* lin2w = (const float*)d_in[7];
    const float* lin2b = (const float*)d_in[8];
    const float* linw  = (const float*)d_in[9];
    const float* linb  = (const float*)d_in[10];
    const float* ow1   = (const float*)d_in[11];
    const float* ob1   = (const float*)d_in[12];
    const float* ow2   = (const float*)d_in[13];
    const float* ob2   = (const float*)d_in[14];
    const int*   z     = (const int*)d_in[15];
    const int*   batch = (const int*)d_in[16];
    const int*   row   = (const int*)d_in[17];
    const int*   col   = row + Ee;
    float* out = (float*)d_out;

    const size_t smem_table = (size_t)(NG * 128 + 128 * 128 + 256 + 4 * 8 * 128 + 4 * 8 * NG) * 4;
    const size_t smem_g128  = (size_t)(128 * 128 + 128 + 64 * 128) * 4;
    const size_t smem_g64   = (size_t)(128 * 64 + 64 + 64 * 128) * 4;
    cudaFuncSetAttribute(k_table, cudaFuncAttributeMaxDynamicSharedMemorySize, (int)smem_table);
    cudaFuncSetAttribute(k_ngemm<128, false, false, false>, cudaFuncAttributeMaxDynamicSharedMemorySize, (int)smem_g128);
    cudaFuncSetAttribute(k_ngemm<128, true,  true,  false>, cudaFuncAttributeMaxDynamicSharedMemorySize, (int)smem_g128);
    cudaFuncSetAttribute(k_ngemm<128, true,  false, true >, cudaFuncAttributeMaxDynamicSharedMemorySize, (int)smem_g128);
    cudaFuncSetAttribute(k_ngemm<64,  true,  true,  false>, cudaFuncAttributeMaxDynamicSharedMemorySize, (int)smem_g64);

    float *ph, *px, *px2, *pagg, *ph2;
    cudaGetSymbolAddress((void**)&ph,   g_h);
    cudaGetSymbolAddress((void**)&px,   g_x);
    cudaGetSymbolAddress((void**)&px2,  g_x2);
    cudaGetSymbolAddress((void**)&pagg, g_agg);
    cudaGetSymbolAddress((void**)&ph2,  g_h2);

    cudaMemsetAsync(out, 0, Gg * sizeof(float), 0);
    k_embed<<<(Nn * 32 + 255) / 256, 256>>>(emb, z);
    k_geom <<<(Ee + 255) / 256, 256>>>(pos, row, col);
    k_table<<<dim3(32, NI), 128, smem_table>>>(w1, b1, w2, b2);

    for (int i = 0; i < NI; i++) {
        k_ngemm<128, false, false, false><<<296, 256, smem_g128>>>(ph, lin1w + (size_t)i * 128 * 128, nullptr, px, Nn);
        cudaMemsetAsync(pagg, 0, (size_t)Nn * Hh * sizeof(float), 0);
        k_edge<<<1184, 256>>>(i, row, col);
        k_ngemm<128, true, true, false><<<296, 256, smem_g128>>>(pagg, lin2w + (size_t)i * 128 * 128, lin2b + i * 128, px2, Nn);
        k_ngemm<128, true, false, true><<<296, 256, smem_g128>>>(px2, linw + (size_t)i * 128 * 128, linb + i * 128, ph, Nn);
    }

    k_ngemm<64, true, true, false><<<296, 256, smem_g64>>>(ph, ow1, ob1, ph2, Nn);
    k_energy<<<(Nn * 32 + 255) / 256, 256>>>(ow2, ob2, batch, out);
}

// round 2
// speedup vs baseline: 1.1230x; 1.1230x over previous
#include <cuda_runtime.h>
#include <math.h>

#define Nn 50000
#define Ee 800000
#define Hh 128
#define Gg 512
#define NG 50
#define NI 6
#define TT 8192

#define TAB_DMAX 8.6605f
#define DTf      (TAB_DMAX / 8191.0f)
#define INV_DT   (8191.0f / TAB_DMAX)
#define GDELTA   (10.0f / 49.0f)
#define PI_OC    0.3141592653589793f

// ---------------- scratch (static device globals; no allocs allowed) -------
__device__ __align__(16) float g_h  [Nn * Hh];
__device__ __align__(16) float g_x  [Nn * Hh];
__device__ __align__(16) float g_x2 [Nn * Hh];
__device__ __align__(16) float g_agg[Nn * Hh];
__device__ __align__(16) float g_h2 [Nn * 64];
__device__ __align__(16) float g_tab[(size_t)NI * TT * Hh];   // 25.2 MB

// CSR scratch
__device__ int   g_deg [Nn];
__device__ int   g_cur [Nn];
__device__ int   g_off [Nn + 1];
__device__ int   g_ecol[Ee];
__device__ int   g_ei0 [Ee];
__device__ float g_efr [Ee];

__device__ __forceinline__ float sspf(float v) {
    float sp = (v > 15.0f) ? v : log1pf(expf(v));
    return sp - 0.6931471805599453f;
}

// ---------------- h = emb[z] ------------------------------------------------
__global__ void k_embed(const float* __restrict__ emb, const int* __restrict__ z) {
    int i = blockIdx.x * blockDim.x + threadIdx.x;
    if (i >= Nn * 32) return;
    int n = i >> 5, c = i & 31;
    ((float4*)g_h)[i] = ((const float4*)emb)[(size_t)z[n] * 32 + c];
}

// ---------------- CSR build --------------------------------------------------
__global__ void k_deg(const int* __restrict__ row) {
    int e = blockIdx.x * blockDim.x + threadIdx.x;
    if (e < Ee) atomicAdd(&g_deg[row[e]], 1);
}

// single-block exclusive scan over g_deg -> g_off
__global__ void k_scan() {
    __shared__ int part[1024];
    int t = threadIdx.x;
    const int CH = (Nn + 1023) / 1024;   // 49
    int base = t * CH;
    int s = 0;
    for (int i = 0; i < CH; i++) {
        int idx = base + i;
        if (idx < Nn) s += g_deg[idx];
    }
    part[t] = s;
    __syncthreads();
    // Hillis-Steele inclusive scan
    for (int o = 1; o < 1024; o <<= 1) {
        int v = (t >= o) ? part[t - o] : 0;
        __syncthreads();
        part[t] += v;
        __syncthreads();
    }
    int run = part[t] - s;   // exclusive prefix of this chunk
    for (int i = 0; i < CH; i++) {
        int idx = base + i;
        if (idx < Nn) { g_off[idx] = run; run += g_deg[idx]; }
    }
    if (t == 1023) g_off[Nn] = Ee;
}

// scatter edges into CSR slots; compute distance -> (i0, frac) on the fly
__global__ void k_scatter(const float* __restrict__ pos,
                          const int* __restrict__ row, const int* __restrict__ col) {
    int e = blockIdx.x * blockDim.x + threadIdx.x;
    if (e >= Ee) return;
    int r = row[e], c = col[e];
    float dx = pos[3 * r + 0] - pos[3 * c + 0];
    float dy = pos[3 * r + 1] - pos[3 * c + 1];
    float dz = pos[3 * r + 2] - pos[3 * c + 2];
    float d = sqrtf(fmaf(dx, dx, fmaf(dy, dy, fmaf(dz, dz, 1e-12f))));
    float tp = d * INV_DT;
    int i0 = (int)tp;
    if (i0 > TT - 2) i0 = TT - 2;
    int s = g_off[r] + atomicAdd(&g_cur[r], 1);
    g_ecol[s] = c;
    g_ei0[s]  = i0;
    g_efr[s]  = tp - (float)i0;
}

// ---------------- build filter tables: tab[i][t][:] = filter_i(d_t) ---------
__global__ void k_table(const float* __restrict__ w1, const float* __restrict__ b1,
                        const float* __restrict__ w2, const float* __restrict__ b2) {
    extern __shared__ float sm[];
    float* w1s = sm;                    // NG*128
    float* w2s = w1s + NG * 128;        // 128*128
    float* b1s = w2s + 128 * 128;       // 128
    float* b2s = b1s + 128;             // 128
    float* ts  = b2s + 128;             // 4*8*128
    float* rs  = ts + 4 * 8 * 128;      // 4*8*NG

    int it = blockIdx.y;
    const float* W1 = w1 + (size_t)it * NG * 128;
    const float* W2 = w2 + (size_t)it * 128 * 128;
    for (int j = threadIdx.x; j < NG * 128; j += blockDim.x) w1s[j] = W1[j];
    for (int j = threadIdx.x; j < 128 * 128; j += blockDim.x) w2s[j] = W2[j];
    if (threadIdx.x < 128) {
        b1s[threadIdx.x] = b1[it * 128 + threadIdx.x];
        b2s[threadIdx.x] = b2[it * 128 + threadIdx.x];
    }
    __syncthreads();

    int warp = threadIdx.x >> 5, lane = threadIdx.x & 31;
    float* tw = ts + warp * 8 * 128;
    float* rw = rs + warp * 8 * NG;
    const float GCO = -0.5f / (GDELTA * GDELTA);

    for (int base = (blockIdx.x * 4 + warp) * 8; base < TT; base += gridDim.x * 32) {
        for (int j = lane; j < 8 * NG; j += 32) {
            int e = j / NG, k = j - e * NG;
            float d = (float)(base + e) * DTf;
            float u = d - (float)k * GDELTA;
            rw[j] = expf(GCO * u * u);
        }
        __syncwarp();

        float4 acc[8];
        float4 bb = *(const float4*)&b1s[4 * lane];
        #pragma unroll
        for (int e = 0; e < 8; e++) acc[e] = bb;
        for (int k = 0; k < NG; k++) {
            float4 w = *(const float4*)&w1s[k * 128 + 4 * lane];
            #pragma unroll
            for (int e = 0; e < 8; e++) {
                float r = rw[e * NG + k];
                acc[e].x = fmaf(r, w.x, acc[e].x);
                acc[e].y = fmaf(r, w.y, acc[e].y);
                acc[e].z = fmaf(r, w.z, acc[e].z);
                acc[e].w = fmaf(r, w.w, acc[e].w);
            }
        }
        #pragma unroll
        for (int e = 0; e < 8; e++) {
            float4 v;
            v.x = sspf(acc[e].x); v.y = sspf(acc[e].y);
            v.z = sspf(acc[e].z); v.w = sspf(acc[e].w);
            *(float4*)&tw[e * 128 + 4 * lane] = v;
        }
        __syncwarp();

        float4 bb2 = *(const float4*)&b2s[4 * lane];
        #pragma unroll
        for (int e = 0; e < 8; e++) acc[e] = bb2;
        for (int k = 0; k < 128; k++) {
            float4 w = *(const float4*)&w2s[k * 128 + 4 * lane];
            #pragma unroll
            for (int e = 0; e < 8; e++) {
                float t = tw[e * 128 + k];
                acc[e].x = fmaf(t, w.x, acc[e].x);
                acc[e].y = fmaf(t, w.y, acc[e].y);
                acc[e].z = fmaf(t, w.z, acc[e].z);
                acc[e].w = fmaf(t, w.w, acc[e].w);
            }
        }
        #pragma unroll
        for (int e = 0; e < 8; e++) {
            float d = (float)(base + e) * DTf;
            float Cc = 0.5f * (cosf(d * PI_OC) + 1.0f);
            float4 v = acc[e];
            v.x *= Cc; v.y *= Cc; v.z *= Cc; v.w *= Cc;
            *(float4*)&g_tab[((size_t)it * TT + (base + e)) * 128 + 4 * lane] = v;
        }
        __syncwarp();
    }
}

// ---------------- generic node GEMM: out = op(in[M,128] @ W[128,NOUT] + b) --
template<int NOUT, bool BIAS, bool ACT, bool RES>
__global__ void k_ngemm(const float* __restrict__ in, const float* __restrict__ W,
                        const float* __restrict__ bias, float* __restrict__ out, int M) {
    constexpr int CG = NOUT / 4;
    constexpr int RG = 256 / CG;
    constexpr int TM = 64 / RG;
    extern __shared__ float sm[];
    float* Ws = sm;                 // 128*NOUT
    float* Bs = Ws + 128 * NOUT;    // NOUT
    float* As = Bs + NOUT;          // 64*128

    for (int j = threadIdx.x; j < (128 * NOUT) / 4; j += 256)
        ((float4*)Ws)[j] = ((const float4*)W)[j];
    if (BIAS) {
        for (int j = threadIdx.x; j < NOUT; j += 256) Bs[j] = bias[j];
    }
    int colg = threadIdx.x % CG;
    int rowg = threadIdx.x / CG;

    for (int mBase = blockIdx.x * 64; mBase < M; mBase += gridDim.x * 64) {
        __syncthreads();
        for (int j = threadIdx.x; j < 2048; j += 256) {
            int r = j >> 5;
            int gr = mBase + r;
            ((float4*)As)[j] = (gr < M) ? ((const float4*)in)[(size_t)gr * 32 + (j & 31)]
                                        : make_float4(0.f, 0.f, 0.f, 0.f);
        }
        __syncthreads();

        float4 acc[TM];
        #pragma unroll
        for (int r = 0; r < TM; r++) acc[r] = make_float4(0.f, 0.f, 0.f, 0.f);
        #pragma unroll 4
        for (int k = 0; k < 128; k++) {
            float4 w = *(const float4*)&Ws[k * NOUT + 4 * colg];
            #pragma unroll
            for (int r = 0; r < TM; r++) {
                float a = As[(rowg * TM + r) * 128 + k];
                acc[r].x = fmaf(a, w.x, acc[r].x);
                acc[r].y = fmaf(a, w.y, acc[r].y);
                acc[r].z = fmaf(a, w.z, acc[r].z);
                acc[r].w = fmaf(a, w.w, acc[r].w);
            }
        }
        #pragma unroll
        for (int r = 0; r < TM; r++) {
            int gr = mBase + rowg * TM + r;
            if (gr < M) {
                float4 v = acc[r];
                if (BIAS) {
                    v.x += Bs[4 * colg + 0]; v.y += Bs[4 * colg + 1];
                    v.z += Bs[4 * colg + 2]; v.w += Bs[4 * colg + 3];
                }
                if (ACT) { v.x = sspf(v.x); v.y = sspf(v.y); v.z = sspf(v.z); v.w = sspf(v.w); }
                float4* dst = (float4*)(out + (size_t)gr * NOUT + 4 * colg);
                if (RES) { float4 o = *dst; v.x += o.x; v.y += o.y; v.z += o.z; v.w += o.w; }
                *dst = v;
            }
        }
    }
}

// ---------------- aggregation: one warp per node, CSR gather ----------------
__global__ void k_agg(int it) {
    const float4* __restrict__ tab = (const float4*)(g_tab + (size_t)it * TT * Hh);
    int w = (blockIdx.x * blockDim.x + threadIdx.x) >> 5;
    if (w >= Nn) return;
    int lane = threadIdx.x & 31;
    int s   = g_off[w];
    int end = g_off[w + 1];
    float4 acc = make_float4(0.f, 0.f, 0.f, 0.f);
    for (; s < end; s++) {
        int   c  = __ldg(&g_ecol[s]);
        int   i0 = __ldg(&g_ei0[s]);
        float fr = __ldg(&g_efr[s]);
        float4 a = tab[(size_t)i0 * 32 + lane];
        float4 b = tab[(size_t)i0 * 32 + 32 + lane];
        float4 x = ((const float4*)g_x)[(size_t)c * 32 + lane];
        acc.x = fmaf(x.x, fmaf(fr, b.x - a.x, a.x), acc.x);
        acc.y = fmaf(x.y, fmaf(fr, b.y - a.y, a.y), acc.y);
        acc.z = fmaf(x.z, fmaf(fr, b.z - a.z, a.z), acc.z);
        acc.w = fmaf(x.w, fmaf(fr, b.w - a.w, a.w), acc.w);
    }
    ((float4*)g_agg)[(size_t)w * 32 + lane] = acc;
}

// ---------------- readout: energy[batch[n]] += h2[n] . ow2 + ob2 ------------
__global__ void k_energy(const float* __restrict__ ow2, const float* __restrict__ ob2,
                         const int* __restrict__ batch, float* __restrict__ out) {
    int idx = blockIdx.x * blockDim.x + threadIdx.x;
    int n = idx >> 5;
    if (n >= Nn) return;
    int lane = idx & 31;
    float2 hv = ((const float2*)(g_h2 + (size_t)n * 64))[lane];
    float2 wv = ((const float2*)ow2)[lane];
    float s = hv.x * wv.x + hv.y * wv.y;
    #pragma unroll
    for (int o = 16; o; o >>= 1) s += __shfl_down_sync(0xffffffffu, s, o);
    if (lane == 0) atomicAdd(&out[batch[n]], s + ob2[0]);
}

// ---------------------------------------------------------------------------
extern "C" void kernel_launch(void* const* d_in, const int* in_sizes, int n_in,
                              void* d_out, int out_size) {
    const float* pos   = (const float*)d_in[0];
    const float* emb   = (const float*)d_in[1];
    const float* w1    = (const float*)d_in[2];
    const float* b1    = (const float*)d_in[3];
    const float* w2    = (const float*)d_in[4];
    const float* b2    = (const float*)d_in[5];
    const float* lin1w = (const float*)d_in[6];
    const float* lin2w = (const float*)d_in[7];
    const float* lin2b = (const float*)d_in[8];
    const float* linw  = (const float*)d_in[9];
    const float* linb  = (const float*)d_in[10];
    const float* ow1   = (const float*)d_in[11];
    const float* ob1   = (const float*)d_in[12];
    const float* ow2   = (const float*)d_in[13];
    const float* ob2   = (const float*)d_in[14];
    const int*   z     = (const int*)d_in[15];
    const int*   batch = (const int*)d_in[16];
    const int*   row   = (const int*)d_in[17];
    const int*   col   = row + Ee;
    float* out = (float*)d_out;

    const size_t smem_table = (size_t)(NG * 128 + 128 * 128 + 256 + 4 * 8 * 128 + 4 * 8 * NG) * 4;
    const size_t smem_g128  = (size_t)(128 * 128 + 128 + 64 * 128) * 4;
    const size_t smem_g64   = (size_t)(128 * 64 + 64 + 64 * 128) * 4;
    cudaFuncSetAttribute(k_table, cudaFuncAttributeMaxDynamicSharedMemorySize, (int)smem_table);
    cudaFuncSetAttribute(k_ngemm<128, false, false, false>, cudaFuncAttributeMaxDynamicSharedMemorySize, (int)smem_g128);
    cudaFuncSetAttribute(k_ngemm<128, true,  true,  false>, cudaFuncAttributeMaxDynamicSharedMemorySize, (int)smem_g128);
    cudaFuncSetAttribute(k_ngemm<128, true,  false, true >, cudaFuncAttributeMaxDynamicSharedMemorySize, (int)smem_g128);
    cudaFuncSetAttribute(k_ngemm<64,  true,  true,  false>, cudaFuncAttributeMaxDynamicSharedMemorySize, (int)smem_g64);

    float *ph, *px, *px2, *pagg, *ph2;
    cudaGetSymbolAddress((void**)&ph,   g_h);
    cudaGetSymbolAddress((void**)&px,   g_x);
    cudaGetSymbolAddress((void**)&px2,  g_x2);
    cudaGetSymbolAddress((void**)&pagg, g_agg);
    cudaGetSymbolAddress((void**)&ph2,  g_h2);
    int *pdeg, *pcur;
    cudaGetSymbolAddress((void**)&pdeg, g_deg);
    cudaGetSymbolAddress((void**)&pcur, g_cur);

    cudaMemsetAsync(out, 0, Gg * sizeof(float), 0);
    cudaMemsetAsync(pdeg, 0, Nn * sizeof(int), 0);
    cudaMemsetAsync(pcur, 0, Nn * sizeof(int), 0);

    k_embed<<<(Nn * 32 + 255) / 256, 256>>>(emb, z);
    k_deg  <<<(Ee + 255) / 256, 256>>>(row);
    k_scan <<<1, 1024>>>();
    k_scatter<<<(Ee + 255) / 256, 256>>>(pos, row, col);
    k_table<<<dim3(64, NI), 128, smem_table>>>(w1, b1, w2, b2);

    for (int i = 0; i < NI; i++) {
        k_ngemm<128, false, false, false><<<296, 256, smem_g128>>>(ph, lin1w + (size_t)i * 128 * 128, nullptr, px, Nn);
        k_agg<<<(Nn * 32 + 255) / 256, 256>>>(i);
        k_ngemm<128, true, true, false><<<296, 256, smem_g128>>>(pagg, lin2w + (size_t)i * 128 * 128, lin2b + i * 128, px2, Nn);
        k_ngemm<128, true, false, true><<<296, 256, smem_g128>>>(px2, linw + (size_t)i * 128 * 128, linb + i * 128, ph, Nn);
    }

    k_ngemm<64, true, true, false><<<296, 256, smem_g64>>>(ph, ow1, ob1, ph2, Nn);
    k_energy<<<(Nn * 32 + 255) / 256, 256>>>(ow2, ob2, batch, out);
}

// round 3
// speedup vs baseline: 1.7883x; 1.5924x over previous
#include <cuda_runtime.h>
#include <math.h>

#define Nn 50000
#define Ee 800000
#define Hh 128
#define Gg 512
#define NG 50
#define NI 6
#define TT 8192
#define TT2 65536

#define TAB_DMAX 8.6605f
#define DTf      (TAB_DMAX / 8191.0f)
#define INV_DT   (8191.0f / TAB_DMAX)
#define INV_DT2  (65535.0f / TAB_DMAX)
#define GDELTA   (10.0f / 49.0f)
#define PI_OC    0.3141592653589793f

typedef unsigned long long ull;

// ---------------- scratch (static device globals; no allocs allowed) -------
__device__ __align__(16) float g_h  [Nn * Hh];
__device__ __align__(16) float g_x  [Nn * Hh];
__device__ __align__(16) float g_x2 [Nn * Hh];
__device__ __align__(16) float g_agg[Nn * Hh];
__device__ __align__(16) float g_h2 [Nn * 64];
__device__ __align__(16) float g_tab [(size_t)NI * TT  * Hh];  // 25.2 MB (coarse, lerp source)
__device__ __align__(16) float g_tab2[(size_t)NI * TT2 * Hh];  // 201 MB (fine, nearest)

// CSR scratch
__device__ int  g_deg [Nn];
__device__ int  g_cur [Nn];
__device__ int  g_off [Nn + 1];
__device__ ull  g_meta[Ee];   // low32 = col, high32 = fine table index

__device__ __forceinline__ float sspf(float v) {
    float sp = (v > 15.0f) ? v : log1pf(expf(v));
    return sp - 0.6931471805599453f;
}

// ---- packed f32x2 helpers ---------------------------------------------------
__device__ __forceinline__ ull f2fma(ull a, ull b, ull c) {
    ull d; asm("fma.rn.f32x2 %0, %1, %2, %3;" : "=l"(d) : "l"(a), "l"(b), "l"(c)); return d;
}
__device__ __forceinline__ ull f2add(ull a, ull b) {
    ull d; asm("add.rn.f32x2 %0, %1, %2;" : "=l"(d) : "l"(a), "l"(b)); return d;
}
__device__ __forceinline__ ull f2dup(float x) {
    ull d; asm("mov.b64 %0, {%1, %1};" : "=l"(d) : "f"(x)); return d;
}
__device__ __forceinline__ float2 f2unpack(ull v) {
    float2 r; asm("mov.b64 {%0, %1}, %2;" : "=f"(r.x), "=f"(r.y) : "l"(v)); return r;
}

// ---------------- h = emb[z] ------------------------------------------------
__global__ void k_embed(const float* __restrict__ emb, const int* __restrict__ z) {
    int i = blockIdx.x * blockDim.x + threadIdx.x;
    if (i >= Nn * 32) return;
    int n = i >> 5, c = i & 31;
    ((float4*)g_h)[i] = ((const float4*)emb)[(size_t)z[n] * 32 + c];
}

// ---------------- CSR build --------------------------------------------------
__global__ void k_deg(const int* __restrict__ row) {
    int e = blockIdx.x * blockDim.x + threadIdx.x;
    if (e < Ee) atomicAdd(&g_deg[row[e]], 1);
}

__global__ void k_scan() {
    __shared__ int part[1024];
    int t = threadIdx.x;
    const int CH = (Nn + 1023) / 1024;
    int base = t * CH;
    int s = 0;
    for (int i = 0; i < CH; i++) {
        int idx = base + i;
        if (idx < Nn) s += g_deg[idx];
    }
    part[t] = s;
    __syncthreads();
    for (int o = 1; o < 1024; o <<= 1) {
        int v = (t >= o) ? part[t - o] : 0;
        __syncthreads();
        part[t] += v;
        __syncthreads();
    }
    int run = part[t] - s;
    for (int i = 0; i < CH; i++) {
        int idx = base + i;
        if (idx < Nn) { g_off[idx] = run; run += g_deg[idx]; }
    }
    if (t == 1023) g_off[Nn] = Ee;
}

__global__ void k_scatter(const float* __restrict__ pos,
                          const int* __restrict__ row, const int* __restrict__ col) {
    int e = blockIdx.x * blockDim.x + threadIdx.x;
    if (e >= Ee) return;
    int r = row[e], c = col[e];
    float dx = pos[3 * r + 0] - pos[3 * c + 0];
    float dy = pos[3 * r + 1] - pos[3 * c + 1];
    float dz = pos[3 * r + 2] - pos[3 * c + 2];
    float d = sqrtf(fmaf(dx, dx, fmaf(dy, dy, fmaf(dz, dz, 1e-12f))));
    int i0 = (int)(d * INV_DT2 + 0.5f);
    if (i0 > TT2 - 1) i0 = TT2 - 1;
    int s = g_off[r] + atomicAdd(&g_cur[r], 1);
    g_meta[s] = (ull)(unsigned)c | ((ull)(unsigned)i0 << 32);
}

// ---------------- build coarse filter tables --------------------------------
__global__ void k_table(const float* __restrict__ w1, const float* __restrict__ b1,
                        const float* __restrict__ w2, const float* __restrict__ b2) {
    extern __shared__ float sm[];
    float* w1s = sm;                    // NG*128
    float* w2s = w1s + NG * 128;        // 128*128
    float* b1s = w2s + 128 * 128;       // 128
    float* b2s = b1s + 128;             // 128
    float* ts  = b2s + 128;             // 4*8*128
    float* rs  = ts + 4 * 8 * 128;      // 4*8*NG

    int it = blockIdx.y;
    const float* W1 = w1 + (size_t)it * NG * 128;
    const float* W2 = w2 + (size_t)it * 128 * 128;
    for (int j = threadIdx.x; j < NG * 128; j += blockDim.x) w1s[j] = W1[j];
    for (int j = threadIdx.x; j < 128 * 128; j += blockDim.x) w2s[j] = W2[j];
    if (threadIdx.x < 128) {
        b1s[threadIdx.x] = b1[it * 128 + threadIdx.x];
        b2s[threadIdx.x] = b2[it * 128 + threadIdx.x];
    }
    __syncthreads();

    int warp = threadIdx.x >> 5, lane = threadIdx.x & 31;
    float* tw = ts + warp * 8 * 128;
    float* rw = rs + warp * 8 * NG;
    const float GCO = -0.5f / (GDELTA * GDELTA);

    for (int base = (blockIdx.x * 4 + warp) * 8; base < TT; base += gridDim.x * 32) {
        for (int j = lane; j < 8 * NG; j += 32) {
            int e = j / NG, k = j - e * NG;
            float d = (float)(base + e) * DTf;
            float u = d - (float)k * GDELTA;
            rw[j] = expf(GCO * u * u);
        }
        __syncwarp();

        float4 acc[8];
        float4 bb = *(const float4*)&b1s[4 * lane];
        #pragma unroll
        for (int e = 0; e < 8; e++) acc[e] = bb;
        for (int k = 0; k < NG; k++) {
            float4 w = *(const float4*)&w1s[k * 128 + 4 * lane];
            #pragma unroll
            for (int e = 0; e < 8; e++) {
                float r = rw[e * NG + k];
                acc[e].x = fmaf(r, w.x, acc[e].x);
                acc[e].y = fmaf(r, w.y, acc[e].y);
                acc[e].z = fmaf(r, w.z, acc[e].z);
                acc[e].w = fmaf(r, w.w, acc[e].w);
            }
        }
        #pragma unroll
        for (int e = 0; e < 8; e++) {
            float4 v;
            v.x = sspf(acc[e].x); v.y = sspf(acc[e].y);
            v.z = sspf(acc[e].z); v.w = sspf(acc[e].w);
            *(float4*)&tw[e * 128 + 4 * lane] = v;
        }
        __syncwarp();

        float4 bb2 = *(const float4*)&b2s[4 * lane];
        #pragma unroll
        for (int e = 0; e < 8; e++) acc[e] = bb2;
        for (int k = 0; k < 128; k++) {
            float4 w = *(const float4*)&w2s[k * 128 + 4 * lane];
            #pragma unroll
            for (int e = 0; e < 8; e++) {
                float t = tw[e * 128 + k];
                acc[e].x = fmaf(t, w.x, acc[e].x);
                acc[e].y = fmaf(t, w.y, acc[e].y);
                acc[e].z = fmaf(t, w.z, acc[e].z);
                acc[e].w = fmaf(t, w.w, acc[e].w);
            }
        }
        #pragma unroll
        for (int e = 0; e < 8; e++) {
            float d = (float)(base + e) * DTf;
            float Cc = 0.5f * (cosf(d * PI_OC) + 1.0f);
            float4 v = acc[e];
            v.x *= Cc; v.y *= Cc; v.z *= Cc; v.w *= Cc;
            *(float4*)&g_tab[((size_t)it * TT + (base + e)) * 128 + 4 * lane] = v;
        }
        __syncwarp();
    }
}

// ---------------- expand coarse table -> fine (nearest-sample) table --------
__global__ void k_expand() {
    long long i = (long long)blockIdx.x * blockDim.x + threadIdx.x;
    if (i >= (long long)NI * TT2 * 32) return;
    int lane = (int)(i & 31);
    long long n = i >> 5;
    int t2 = (int)(n & (TT2 - 1));
    int it = (int)(n >> 16);
    float tp = (float)t2 * (8191.0f / 65535.0f);
    int i0 = (int)tp;
    if (i0 > TT - 2) i0 = TT - 2;
    float fr = tp - (float)i0;
    const float4* src = (const float4*)(g_tab + ((size_t)it * TT + i0) * Hh);
    float4 a = src[lane], b = src[32 + lane];
    float4 v;
    v.x = fmaf(fr, b.x - a.x, a.x);
    v.y = fmaf(fr, b.y - a.y, a.y);
    v.z = fmaf(fr, b.z - a.z, a.z);
    v.w = fmaf(fr, b.w - a.w, a.w);
    ((float4*)g_tab2)[n * 32 + lane] = v;
}

// ---------------- node GEMM with packed f32x2 FMA ----------------------------
template<int NOUT, bool BIAS, bool ACT, bool RES>
__global__ void k_ngemm(const float* __restrict__ in, const float* __restrict__ W,
                        const float* __restrict__ bias, float* __restrict__ out, int M) {
    constexpr int CG = NOUT / 4;
    constexpr int RG = 256 / CG;
    constexpr int TM = 64 / RG;
    extern __shared__ float sm[];
    float* Ws = sm;                 // 128*NOUT
    float* Bs = Ws + 128 * NOUT;    // NOUT
    float* As = Bs + NOUT;          // 64*128

    for (int j = threadIdx.x; j < (128 * NOUT) / 4; j += 256)
        ((float4*)Ws)[j] = ((const float4*)W)[j];
    if (BIAS) {
        for (int j = threadIdx.x; j < NOUT; j += 256) Bs[j] = bias[j];
    }
    int colg = threadIdx.x % CG;
    int rowg = threadIdx.x / CG;

    for (int mBase = blockIdx.x * 64; mBase < M; mBase += gridDim.x * 64) {
        __syncthreads();
        for (int j = threadIdx.x; j < 2048; j += 256) {
            int r = j >> 5;
            int gr = mBase + r;
            ((float4*)As)[j] = (gr < M) ? ((const float4*)in)[(size_t)gr * 32 + (j & 31)]
                                        : make_float4(0.f, 0.f, 0.f, 0.f);
        }
        __syncthreads();

        ull acc01[TM], acc23[TM];
        #pragma unroll
        for (int r = 0; r < TM; r++) { acc01[r] = 0ull; acc23[r] = 0ull; }

        #pragma unroll 4
        for (int k = 0; k < 128; k++) {
            ulonglong2 wv = *(const ulonglong2*)&Ws[k * NOUT + 4 * colg];
            #pragma unroll
            for (int r = 0; r < TM; r++) {
                ull aa = f2dup(As[(rowg * TM + r) * 128 + k]);
                acc01[r] = f2fma(aa, wv.x, acc01[r]);
                acc23[r] = f2fma(aa, wv.y, acc23[r]);
            }
        }

        #pragma unroll
        for (int r = 0; r < TM; r++) {
            int gr = mBase + rowg * TM + r;
            if (gr < M) {
                float2 p0 = f2unpack(acc01[r]);
                float2 p1 = f2unpack(acc23[r]);
                float4 v = make_float4(p0.x, p0.y, p1.x, p1.y);
                if (BIAS) {
                    v.x += Bs[4 * colg + 0]; v.y += Bs[4 * colg + 1];
                    v.z += Bs[4 * colg + 2]; v.w += Bs[4 * colg + 3];
                }
                if (ACT) { v.x = sspf(v.x); v.y = sspf(v.y); v.z = sspf(v.z); v.w = sspf(v.w); }
                float4* dst = (float4*)(out + (size_t)gr * NOUT + 4 * colg);
                if (RES) { float4 o = *dst; v.x += o.x; v.y += o.y; v.z += o.z; v.w += o.w; }
                *dst = v;
            }
        }
    }
}

// ---------------- aggregation: one warp per node, nearest-table gather ------
__global__ void k_agg(int it) {
    const ulonglong2* __restrict__ tab = (const ulonglong2*)(g_tab2 + (size_t)it * TT2 * Hh);
    const ulonglong2* __restrict__ X   = (const ulonglong2*)g_x;
    int w = (blockIdx.x * blockDim.x + threadIdx.x) >> 5;
    if (w >= Nn) return;
    int lane = threadIdx.x & 31;
    int s   = g_off[w];
    int end = g_off[w + 1];
    ull a0 = 0ull, a1 = 0ull, b0 = 0ull, b1 = 0ull;
    for (; s + 2 <= end; s += 2) {
        ull m0 = g_meta[s], m1 = g_meta[s + 1];
        ulonglong2 t0 = tab[(size_t)(m0 >> 32) * 32 + lane];
        ulonglong2 x0 = X  [(size_t)(unsigned)m0 * 32 + lane];
        ulonglong2 t1 = tab[(size_t)(m1 >> 32) * 32 + lane];
        ulonglong2 x1 = X  [(size_t)(unsigned)m1 * 32 + lane];
        a0 = f2fma(x0.x, t0.x, a0);
        a1 = f2fma(x0.y, t0.y, a1);
        b0 = f2fma(x1.x, t1.x, b0);
        b1 = f2fma(x1.y, t1.y, b1);
    }
    if (s < end) {
        ull m0 = g_meta[s];
        ulonglong2 t0 = tab[(size_t)(m0 >> 32) * 32 + lane];
        ulonglong2 x0 = X  [(size_t)(unsigned)m0 * 32 + lane];
        a0 = f2fma(x0.x, t0.x, a0);
        a1 = f2fma(x0.y, t0.y, a1);
    }
    a0 = f2add(a0, b0);
    a1 = f2add(a1, b1);
    float2 p0 = f2unpack(a0);
    float2 p1 = f2unpack(a1);
    ((float4*)g_agg)[(size_t)w * 32 + lane] = make_float4(p0.x, p0.y, p1.x, p1.y);
}

// ---------------- readout ----------------------------------------------------
__global__ void k_energy(const float* __restrict__ ow2, const float* __restrict__ ob2,
                         const int* __restrict__ batch, float* __restrict__ out) {
    int idx = blockIdx.x * blockDim.x + threadIdx.x;
    int n = idx >> 5;
    if (n >= Nn) return;
    int lane = idx & 31;
    float2 hv = ((const float2*)(g_h2 + (size_t)n * 64))[lane];
    float2 wv = ((const float2*)ow2)[lane];
    float s = hv.x * wv.x + hv.y * wv.y;
    #pragma unroll
    for (int o = 16; o; o >>= 1) s += __shfl_down_sync(0xffffffffu, s, o);
    if (lane == 0) atomicAdd(&out[batch[n]], s + ob2[0]);
}

// ---------------------------------------------------------------------------
extern "C" void kernel_launch(void* const* d_in, const int* in_sizes, int n_in,
                              void* d_out, int out_size) {
    const float* pos   = (const float*)d_in[0];
    const float* emb   = (const float*)d_in[1];
    const float* w1    = (const float*)d_in[2];
    const float* b1    = (const float*)d_in[3];
    const float* w2    = (const float*)d_in[4];
    const float* b2    = (const float*)d_in[5];
    const float* lin1w = (const float*)d_in[6];
    const float* lin2w = (const float*)d_in[7];
    const float* lin2b = (const float*)d_in[8];
    const float* linw  = (const float*)d_in[9];
    const float* linb  = (const float*)d_in[10];
    const float* ow1   = (const float*)d_in[11];
    const float* ob1   = (const float*)d_in[12];
    const float* ow2   = (const float*)d_in[13];
    const float* ob2   = (const float*)d_in[14];
    const int*   z     = (const int*)d_in[15];
    const int*   batch = (const int*)d_in[16];
    const int*   row   = (const int*)d_in[17];
    const int*   col   = row + Ee;
    float* out = (float*)d_out;

    const size_t smem_table = (size_t)(NG * 128 + 128 * 128 + 256 + 4 * 8 * 128 + 4 * 8 * NG) * 4;
    const size_t smem_g128  = (size_t)(128 * 128 + 128 + 64 * 128) * 4;
    const size_t smem_g64   = (size_t)(128 * 64 + 64 + 64 * 128) * 4;
    cudaFuncSetAttribute(k_table, cudaFuncAttributeMaxDynamicSharedMemorySize, (int)smem_table);
    cudaFuncSetAttribute(k_ngemm<128, false, false, false>, cudaFuncAttributeMaxDynamicSharedMemorySize, (int)smem_g128);
    cudaFuncSetAttribute(k_ngemm<128, true,  true,  false>, cudaFuncAttributeMaxDynamicSharedMemorySize, (int)smem_g128);
    cudaFuncSetAttribute(k_ngemm<128, true,  false, true >, cudaFuncAttributeMaxDynamicSharedMemorySize, (int)smem_g128);
    cudaFuncSetAttribute(k_ngemm<64,  true,  true,  false>, cudaFuncAttributeMaxDynamicSharedMemorySize, (int)smem_g64);

    float *ph, *px, *px2, *pagg, *ph2;
    cudaGetSymbolAddress((void**)&ph,   g_h);
    cudaGetSymbolAddress((void**)&px,   g_x);
    cudaGetSymbolAddress((void**)&px2,  g_x2);
    cudaGetSymbolAddress((void**)&pagg, g_agg);
    cudaGetSymbolAddress((void**)&ph2,  g_h2);
    int *pdeg, *pcur;
    cudaGetSymbolAddress((void**)&pdeg, g_deg);
    cudaGetSymbolAddress((void**)&pcur, g_cur);

    cudaMemsetAsync(out, 0, Gg * sizeof(float), 0);
    cudaMemsetAsync(pdeg, 0, Nn * sizeof(int), 0);
    cudaMemsetAsync(pcur, 0, Nn * sizeof(int), 0);

    k_embed<<<(Nn * 32 + 255) / 256, 256>>>(emb, z);
    k_deg  <<<(Ee + 255) / 256, 256>>>(row);
    k_scan <<<1, 1024>>>();
    k_scatter<<<(Ee + 255) / 256, 256>>>(pos, row, col);
    k_table<<<dim3(64, NI), 128, smem_table>>>(w1, b1, w2, b2);
    k_expand<<<(int)(((long long)NI * TT2 * 32 + 255) / 256), 256>>>();

    for (int i = 0; i < NI; i++) {
        k_ngemm<128, false, false, false><<<296, 256, smem_g128>>>(ph, lin1w + (size_t)i * 128 * 128, nullptr, px, Nn);
        k_agg<<<(Nn * 32 + 255) / 256, 256>>>(i);
        k_ngemm<128, true, true, false><<<296, 256, smem_g128>>>(pagg, lin2w + (size_t)i * 128 * 128, lin2b + i * 128, px2, Nn);
        k_ngemm<128, true, false, true><<<296, 256, smem_g128>>>(px2, linw + (size_t)i * 128 * 128, linb + i * 128, ph, Nn);
    }

    k_ngemm<64, true, true, false><<<296, 256, smem_g64>>>(ph, ow1, ob1, ph2, Nn);
    k_energy<<<(Nn * 32 + 255) / 256, 256>>>(ow2, ob2, batch, out);
}